// round 14
// baseline (speedup 1.0000x reference)
#include <cuda_runtime.h>
#include <stdint.h>

// Problem shape (fixed by the reference): B=32, C=3, H=W=1024, patch 256x256.
#define Bn 32
#define Cn 3
#define Hn 1024
#define Wn 1024
#define PH 256
#define PW 256

#define TOTAL  (Bn * Cn * Hn * Wn)   // 100,663,296 floats
#define TOTAL8 (TOTAL / 8)           // 12,582,912 float4-pairs (32B units)

#define NBLOCKS (148 * 16)           // 2368: SM-balanced persistent grid
#define NTHREADS 256

__device__ __forceinline__ void blend4(float4& v, unsigned int base,
                                       int x, int y, unsigned int t,
                                       unsigned int hh, unsigned int ww,
                                       const float* __restrict__ patch,
                                       const float* __restrict__ mask)
{
    int dy = (int)hh - y;
    if (dy >= 0 && dy < PH) {
        int dx0 = (int)ww - x;
        if (dx0 + 3 >= 0 && dx0 < PW) {
            unsigned int pbase = (t * PH + (unsigned)dy) * PW;
            float* pv = &v.x;
            #pragma unroll
            for (int k = 0; k < 4; k++) {
                int dx = dx0 + k;
                if (dx >= 0 && dx < PW) {
                    float m = __ldg(&mask[pbase + dx]);
                    float p = __ldg(&patch[pbase + dx]);
                    pv[k] = fmaf(m, p - pv[k], pv[k]);  // m*p + (1-m)*old
                }
            }
        }
    }
}

__global__ __launch_bounds__(NTHREADS) void paste_kernel(
    const float* __restrict__ bg,
    const float* __restrict__ patch,
    const int* __restrict__ xs,      // JAX x64 disabled: these buffers are int32
    const int* __restrict__ ys,
    const float* __restrict__ mask,
    float* __restrict__ out)
{
    const unsigned int stride = NBLOCKS * NTHREADS;   // 606,208 (in 32B units)

    #pragma unroll 1
    for (unsigned int i8 = blockIdx.x * NTHREADS + threadIdx.x;
         i8 < TOTAL8; i8 += stride)
    {
        unsigned int base = i8 * 8u;          // element index, 32B aligned

        // decompose once for the pair: base = ((b*C + c)*H + hh)*W + ww
        unsigned int ww = base & (Wn - 1);    // 0..1016, pair stays in one row
        unsigned int t  = base >> 10;
        unsigned int hh = t & (Hn - 1);
        t >>= 10;                             // b*C + c
        unsigned int b  = t / Cn;

        float4 v0 = *reinterpret_cast<const float4*>(bg + base);
        float4 v1 = *reinterpret_cast<const float4*>(bg + base + 4);

        int x = __ldg(&xs[b]);
        int y = __ldg(&ys[b]);
        blend4(v0, base,     x, y, t, hh, ww,     patch, mask);
        blend4(v1, base + 4, x, y, t, hh, ww + 4, patch, mask);

        *reinterpret_cast<float4*>(out + base)     = v0;
        *reinterpret_cast<float4*>(out + base + 4) = v1;
    }
}

extern "C" void kernel_launch(void* const* d_in, const int* in_sizes, int n_in,
                              void* d_out, int out_size)
{
    // metadata order: background, patch, x, y, mask
    const float* bg    = (const float*)d_in[0];
    const float* patch = (const float*)d_in[1];
    const int*   xs    = (const int*)d_in[2];
    const int*   ys    = (const int*)d_in[3];
    const float* mask  = (const float*)d_in[4];
    float*       out   = (float*)d_out;

    paste_kernel<<<NBLOCKS, NTHREADS>>>(bg, patch, xs, ys, mask, out);
}

// round 15
// speedup vs baseline: 1.0312x; 1.0312x over previous
#include <cuda_runtime.h>
#include <stdint.h>

// Problem shape (fixed by the reference): B=32, C=3, H=W=1024, patch 256x256.
#define Bn 32
#define Cn 3
#define Hn 1024
#define Wn 1024
#define PH 256
#define PW 256

#define TOTAL  (Bn * Cn * Hn * Wn)   // 100,663,296 floats
#define TOTAL4 (TOTAL / 4)           // 25,165,824 float4s

#define NBLOCKS (148 * 16)           // 2368: SM-balanced persistent grid
#define NTHREADS 256

__device__ __forceinline__ void blend4(float4& v, unsigned int base,
                                       const int* __restrict__ xs,
                                       const int* __restrict__ ys,
                                       const float* __restrict__ patch,
                                       const float* __restrict__ mask)
{
    // decompose: base = ((b*C + c)*H + hh)*W + ww
    unsigned int ww = base & (Wn - 1);
    unsigned int t  = base >> 10;
    unsigned int hh = t & (Hn - 1);
    t >>= 10;                         // b*C + c
    unsigned int b = t / Cn;

    int x = __ldg(&xs[b]);
    int y = __ldg(&ys[b]);
    int dy = (int)hh - y;
    if (dy >= 0 && dy < PH) {
        int dx0 = (int)ww - x;
        if (dx0 + 3 >= 0 && dx0 < PW) {
            unsigned int pbase = (t * PH + (unsigned)dy) * PW;
            float* pv = &v.x;
            #pragma unroll
            for (int k = 0; k < 4; k++) {
                int dx = dx0 + k;
                if (dx >= 0 && dx < PW) {
                    float m = __ldg(&mask[pbase + dx]);
                    float p = __ldg(&patch[pbase + dx]);
                    pv[k] = fmaf(m, p - pv[k], pv[k]);  // m*p + (1-m)*old
                }
            }
        }
    }
}

__global__ __launch_bounds__(NTHREADS) void paste_kernel(
    const float* __restrict__ bg,
    const float* __restrict__ patch,
    const int* __restrict__ xs,      // JAX x64 disabled: these buffers are int32
    const int* __restrict__ ys,
    const float* __restrict__ mask,
    float* __restrict__ out)
{
    const unsigned int stride = NBLOCKS * NTHREADS;   // 606,208

    #pragma unroll 1
    for (unsigned int i4 = blockIdx.x * NTHREADS + threadIdx.x;
         i4 < TOTAL4; i4 += stride)
    {
        unsigned int base = i4 * 4u;          // element index, 16B aligned

        float4 v = *reinterpret_cast<const float4*>(bg + base);
        blend4(v, base, xs, ys, patch, mask);
        // Write-through store: output is never re-read; skip L2 dirty-allocate.
        __stwt(reinterpret_cast<float4*>(out + base), v);
    }
}

extern "C" void kernel_launch(void* const* d_in, const int* in_sizes, int n_in,
                              void* d_out, int out_size)
{
    // metadata order: background, patch, x, y, mask
    const float* bg    = (const float*)d_in[0];
    const float* patch = (const float*)d_in[1];
    const int*   xs    = (const int*)d_in[2];
    const int*   ys    = (const int*)d_in[3];
    const float* mask  = (const float*)d_in[4];
    float*       out   = (float*)d_out;

    paste_kernel<<<NBLOCKS, NTHREADS>>>(bg, patch, xs, ys, mask, out);
}